// round 5
// baseline (speedup 1.0000x reference)
#include <cuda_runtime.h>
#include <math.h>

#define SS 256
#define BB 64
#define HH 512
#define EE 300
#define TT 10
#define G4 2048   // 4*H
#define NCTA 256  // persistent K2 grid

// ---------------- scratch (static device memory; no allocations) ----------------
__device__ float g_xw_f[SS * BB * G4];       // fwd input projections (134 MB)
__device__ float g_xw_b[SS * BB * G4];       // bwd input projections (134 MB)
__device__ float g_h[SS][BB][2 * HH];        // h outputs for K3 (67 MB)
__device__ float g_hcur[2][2][HH][BB];       // [dir][parity][j][b] recurrent carry
__device__ float g_feats[BB][SS][TT];        // emissions
__device__ int   g_epoch;                    // persistent-kernel barrier state
__device__ int   g_arrive;

__device__ __forceinline__ float sigmf(float x) { return 1.0f / (1.0f + expf(-x)); }

// ---------------- K1: fused embedding gather + input projection GEMM ----------------
// out[m][n] = sum_e emb[tok(m)][e] * wih[n][e] + bias[n]
__global__ __launch_bounds__(256) void k1_proj(
    const int* __restrict__ tokens, const float* __restrict__ emb,
    const float* __restrict__ wih_f, const float* __restrict__ b_f,
    const float* __restrict__ wih_b, const float* __restrict__ b_b)
{
    __shared__ float As[20][68];   // [k][m-local]
    __shared__ float Bs[20][68];   // [k][n-local]

    const int tid = threadIdx.x;
    if (blockIdx.x == 0 && blockIdx.y == 0 && tid == 0) {  // reset K2 barrier state
        g_epoch = 0;
        g_arrive = 0;
    }
    const int tx = tid & 15, ty = tid >> 4;
    const int n0 = blockIdx.x * 64;
    const int m0 = blockIdx.y * 64;

    const int arow = tid >> 2;            // 0..63
    const int akk  = (tid & 3) * 5;       // 0,5,10,15
    const int m_g  = m0 + arow;
    const int s_g  = m_g >> 6, b_g = m_g & 63;
    int tok = tokens[b_g * SS + s_g];
    if (tok < 0 || tok >= 30000) tok = 0;
    const float* asrc = emb + (long)tok * EE;

    const int bg = n0 + arow;
    const float* wsrc = (bg < G4) ? (wih_f + (long)bg * EE)
                                  : (wih_b + (long)(bg - G4) * EE);

    float acc[4][4] = {};

    for (int kt = 0; kt < 15; ++kt) {     // K = 300 = 15 * 20
        const int k0 = kt * 20;
#pragma unroll
        for (int l = 0; l < 5; l++) As[akk + l][arow] = asrc[k0 + akk + l];
#pragma unroll
        for (int l = 0; l < 5; l++) Bs[akk + l][arow] = wsrc[k0 + akk + l];
        __syncthreads();
#pragma unroll
        for (int k = 0; k < 20; k++) {
            float4 av = *(const float4*)&As[k][ty * 4];
            float4 bv = *(const float4*)&Bs[k][tx * 4];
            acc[0][0] += av.x * bv.x; acc[0][1] += av.x * bv.y; acc[0][2] += av.x * bv.z; acc[0][3] += av.x * bv.w;
            acc[1][0] += av.y * bv.x; acc[1][1] += av.y * bv.y; acc[1][2] += av.y * bv.z; acc[1][3] += av.y * bv.w;
            acc[2][0] += av.z * bv.x; acc[2][1] += av.z * bv.y; acc[2][2] += av.z * bv.z; acc[2][3] += av.z * bv.w;
            acc[3][0] += av.w * bv.x; acc[3][1] += av.w * bv.y; acc[3][2] += av.w * bv.z; acc[3][3] += av.w * bv.w;
        }
        __syncthreads();
    }

    // coalesced float4 epilogue
    const int g0  = n0 + tx * 4;
    const int dir = g0 >> 11;
    const int gl0 = g0 & 2047;
    const float* bias = dir ? b_b : b_f;
    float* __restrict__ xw = dir ? g_xw_b : g_xw_f;
    const float bx = bias[gl0 + 0], by = bias[gl0 + 1], bz = bias[gl0 + 2], bw = bias[gl0 + 3];
#pragma unroll
    for (int i = 0; i < 4; i++) {
        const int mm = m0 + ty * 4 + i;
        const int s2 = mm >> 6, b2 = mm & 63;
        float4 v = make_float4(acc[i][0] + bx, acc[i][1] + by, acc[i][2] + bz, acc[i][3] + bw);
        *(float4*)&xw[(long)(s2 * BB + b2) * G4 + gl0] = v;
    }
}

// ---------------- K2: persistent LSTM recurrence, all 256 steps, both dirs ----------------
// 256 CTAs x 128 threads. CTA = (dir, slice of 4 hidden units = 16 gate rows).
// whh slice lives in SMEM for the whole kernel. Cross-step sync = global spin barrier.
// Thread (tu, tb2) owns unit (slice*4+tu) x batches {2*tb2, 2*tb2+1}: the i/f/g/o
// quadrants of its unit are its own accumulators -> cell update is thread-local.
#define K2_SMEM ((512 * 16 + 2 * 64 * 68) * 4)   // ws + double-buffered hs = 66 KB

__global__ __launch_bounds__(128, 2) void k2_persist(
    const float* __restrict__ whh_f, const float* __restrict__ whh_b,
    const int* __restrict__ lengths)
{
    extern __shared__ float sm[];
    float (*ws)[16]      = (float (*)[16])sm;               // [k][u*4+q]
    float (*hs)[64][68]  = (float (*)[64][68])(sm + 8192);  // [buf][k][b]

    const int cta   = blockIdx.x;
    const int dir   = cta >> 7;
    const int slice = cta & 127;
    const float* __restrict__ whh = dir ? whh_b : whh_f;
    const float* __restrict__ xw  = dir ? g_xw_b : g_xw_f;

    const int tid = threadIdx.x;
    const int tu  = tid & 3;          // local unit 0..3
    const int tb2 = tid >> 2;         // batch pair 0..31
    const int b0 = tb2 * 2, b1 = b0 + 1;
    const int uj = slice * 4 + tu;    // global hidden unit

    // load whh slice: rows q*HH + (slice*4+u), ws[k][u*4+q]
    for (int idx = tid; idx < 16 * 512; idx += 128) {
        const int r = idx >> 9;       // 0..15
        const int k = idx & 511;
        const int u = r >> 2, q = r & 3;
        ws[k][u * 4 + q] = whh[(long)(q * HH + slice * 4 + u) * HH + k];
    }

    const int len0 = lengths[b0];
    const int len1 = lengths[b1];
    float c0 = 0.f, c1 = 0.f, hcar0 = 0.f, hcar1 = 0.f;

    // tile-load assignment for hs: thread -> (row tid>>1, col half (tid&1)*32)
    const int lr = tid >> 1;
    const int lc = (tid & 1) * 32;
    __syncthreads();

    for (int t = 0; t < SS; ++t) {
        const int s = dir ? (SS - 1 - t) : t;

        // prefetch input-projection gates (independent of h)
        float xwv[4][2];
        {
            const long base0 = (long)(s * BB + b0) * G4 + uj;
            const long base1 = (long)(s * BB + b1) * G4 + uj;
#pragma unroll
            for (int q = 0; q < 4; q++) {
                xwv[q][0] = __ldg(&xw[base0 + q * HH]);
                xwv[q][1] = __ldg(&xw[base1 + q * HH]);
            }
        }

        float acc[4][2] = {};
        if (t > 0) {
            const int rp = (t & 1) ^ 1;                       // buffer written at t-1
            const float* __restrict__ hsrc = &g_hcur[dir][rp][0][0];

            // tile 0 -> smem buf 0
#pragma unroll
            for (int l = 0; l < 8; l++) {
                float4 v = __ldcg((const float4*)&hsrc[(0 + lr) * BB + lc + l * 4]);
                *(float4*)&hs[0][lr][lc + l * 4] = v;
            }
            __syncthreads();

            int cb = 0;
            for (int kt = 0; kt < 8; ++kt) {                  // K = 512 = 8 * 64
                float4 pre[8];
                if (kt < 7) {
                    const int k0n = (kt + 1) * 64;
#pragma unroll
                    for (int l = 0; l < 8; l++)
                        pre[l] = __ldcg((const float4*)&hsrc[(k0n + lr) * BB + lc + l * 4]);
                }
                const int k0 = kt * 64;
#pragma unroll
                for (int k = 0; k < 64; k++) {
                    float4 wv = *(const float4*)&ws[k0 + k][tu * 4];
                    float2 hv = *(const float2*)&hs[cb][k][b0];
                    acc[0][0] += wv.x * hv.x; acc[0][1] += wv.x * hv.y;
                    acc[1][0] += wv.y * hv.x; acc[1][1] += wv.y * hv.y;
                    acc[2][0] += wv.z * hv.x; acc[2][1] += wv.z * hv.y;
                    acc[3][0] += wv.w * hv.x; acc[3][1] += wv.w * hv.y;
                }
                if (kt < 7) {
#pragma unroll
                    for (int l = 0; l < 8; l++)
                        *(float4*)&hs[cb ^ 1][lr][lc + l * 4] = pre[l];
                    __syncthreads();
                    cb ^= 1;
                }
            }
        }

        // cell update (thread-local)
        const float i0 = acc[0][0] + xwv[0][0], f0 = acc[1][0] + xwv[1][0];
        const float gg0 = acc[2][0] + xwv[2][0], o0 = acc[3][0] + xwv[3][0];
        const float i1 = acc[0][1] + xwv[0][1], f1 = acc[1][1] + xwv[1][1];
        const float gg1 = acc[2][1] + xwv[2][1], o1 = acc[3][1] + xwv[3][1];

        const float cn0 = sigmf(f0) * c0 + sigmf(i0) * tanhf(gg0);
        const float hn0 = sigmf(o0) * tanhf(cn0);
        const float cn1 = sigmf(f1) * c1 + sigmf(i1) * tanhf(gg1);
        const float hn1 = sigmf(o1) * tanhf(cn1);

        const bool m0k = s < len0, m1k = s < len1;
        c0 = m0k ? cn0 : c0;  hcar0 = m0k ? hn0 : hcar0;
        c1 = m1k ? cn1 : c1;  hcar1 = m1k ? hn1 : hcar1;

        const int wp = t & 1;
        g_hcur[dir][wp][uj][b0] = hcar0;
        g_hcur[dir][wp][uj][b1] = hcar1;
        g_h[s][b0][dir * HH + uj] = m0k ? hn0 : 0.f;
        g_h[s][b1][dir * HH + uj] = m1k ? hn1 : 0.f;

        // global barrier between steps
        if (t < SS - 1) {
            __threadfence();
            __syncthreads();
            if (tid == 0) {
                const int a = atomicAdd(&g_arrive, 1);
                if (a == NCTA * (t + 1) - 1) atomicAdd(&g_epoch, 1);
                while (*(volatile int*)&g_epoch < t + 1) { }
            }
            __syncthreads();
        }
    }
}

// ---------------- K3: emissions feats = h @ w_out^T + b_out ----------------
__global__ __launch_bounds__(256) void k3_feats(
    const float* __restrict__ w_out, const float* __restrict__ b_out)
{
    __shared__ float ws[TT * 1024];
    for (int i = threadIdx.x; i < TT * 1024; i += 256) ws[i] = w_out[i];
    __syncthreads();

    const int widx = blockIdx.x * 8 + (threadIdx.x >> 5);
    const int lane = threadIdx.x & 31;
    const int s = widx >> 6, b = widx & 63;
    const float* hrow = &g_h[s][b][0];

    float acc[TT];
#pragma unroll
    for (int t = 0; t < TT; t++) acc[t] = 0.0f;

#pragma unroll 4
    for (int i = 0; i < 32; i++) {
        const int k = lane + i * 32;
        const float hv = hrow[k];
#pragma unroll
        for (int t = 0; t < TT; t++) acc[t] += hv * ws[t * 1024 + k];
    }
#pragma unroll
    for (int t = 0; t < TT; t++) {
        float v = acc[t];
        v += __shfl_xor_sync(0xffffffffu, v, 16);
        v += __shfl_xor_sync(0xffffffffu, v, 8);
        v += __shfl_xor_sync(0xffffffffu, v, 4);
        v += __shfl_xor_sync(0xffffffffu, v, 2);
        v += __shfl_xor_sync(0xffffffffu, v, 1);
        if (lane == t) g_feats[b][s][t] = v + b_out[t];
    }
}

// ---------------- K4: Viterbi decode + backtrace (one warp per batch) ----------------
// Output written as float32 (harness __output__ dtype) — tags exactly representable.
__global__ __launch_bounds__(32) void k4_viterbi(
    const float* __restrict__ start_t, const float* __restrict__ end_t,
    const float* __restrict__ trans, const int* __restrict__ lengths,
    float* __restrict__ out)
{
    const int b = blockIdx.x;
    const int lane = threadIdx.x;
    __shared__ float fe[SS][TT];
    __shared__ float tr[TT][TT];
    __shared__ float sc[TT];
    __shared__ unsigned char bp[SS][TT];

    for (int i = lane; i < SS * TT; i += 32)
        ((float*)fe)[i] = ((const float*)g_feats[b])[i];
    for (int i = lane; i < TT * TT; i += 32)
        ((float*)tr)[i] = trans[i];
    int len = lengths[b];
    if (len < 0) len = 0; if (len > SS) len = SS;
    __syncwarp();
    if (lane < TT) sc[lane] = start_t[lane] + fe[0][lane];
    __syncwarp();

    for (int s = 1; s < SS; ++s) {
        float best = -1e30f; int arg = 0;
        if (lane < TT) {
#pragma unroll
            for (int i = 0; i < TT; i++) {
                const float c = sc[i] + tr[i][lane];
                if (c > best) { best = c; arg = i; }   // first-max, matches jnp.argmax
            }
        }
        __syncwarp();
        if (lane < TT) {
            if (s < len) { sc[lane] = best + fe[s][lane]; bp[s][lane] = (unsigned char)arg; }
            else         { bp[s][lane] = (unsigned char)lane; }
        }
        __syncwarp();
    }

    if (lane == 0) {
        float bestv = -1e30f; int last = 0;
        for (int j = 0; j < TT; j++) {
            const float v = sc[j] + end_t[j];
            if (v > bestv) { bestv = v; last = j; }
        }
        int cur = last;
        for (int s = SS - 1; s >= 1; --s) {
            out[b * SS + s] = (float)((s < len) ? cur : 0);
            cur = bp[s][cur];
        }
        out[b * SS + 0] = (float)cur;
    }
}

// ---------------- host ----------------
static int find_slot(const int* sz, int n, int want, int which, int fallback) {
    int seen = 0;
    for (int i = 0; i < n; i++)
        if (sz[i] == want) { if (seen == which) return i; seen++; }
    return fallback;
}

extern "C" void kernel_launch(void* const* d_in, const int* in_sizes, int n_in,
                              void* d_out, int out_size)
{
    const int i_tok  = find_slot(in_sizes, n_in, SS * BB,      0, 0);
    const int i_len  = find_slot(in_sizes, n_in, BB,           0, 1);
    const int i_emb  = find_slot(in_sizes, n_in, 30000 * EE,   0, 2);
    const int i_wif  = find_slot(in_sizes, n_in, G4 * EE,      0, 3);
    const int i_whf  = find_slot(in_sizes, n_in, G4 * HH,      0, 4);
    const int i_bf   = find_slot(in_sizes, n_in, G4,           0, 5);
    const int i_wib  = find_slot(in_sizes, n_in, G4 * EE,      1, 6);
    const int i_whb  = find_slot(in_sizes, n_in, G4 * HH,      1, 7);
    const int i_bb   = find_slot(in_sizes, n_in, G4,           1, 8);
    const int i_wout = find_slot(in_sizes, n_in, TT * 2 * HH,  0, 9);
    const int i_bout = find_slot(in_sizes, n_in, TT,           0, 10);
    const int i_st   = find_slot(in_sizes, n_in, TT,           1, 11);
    const int i_en   = find_slot(in_sizes, n_in, TT,           2, 12);
    const int i_tr   = find_slot(in_sizes, n_in, TT * TT,      0, 13);

    const int*   tokens  = (const int*)  d_in[i_tok];
    const int*   lens    = (const int*)  d_in[i_len];
    const float* emb     = (const float*)d_in[i_emb];
    const float* wih_f   = (const float*)d_in[i_wif];
    const float* whh_f   = (const float*)d_in[i_whf];
    const float* b_f     = (const float*)d_in[i_bf];
    const float* wih_b   = (const float*)d_in[i_wib];
    const float* whh_b   = (const float*)d_in[i_whb];
    const float* b_b     = (const float*)d_in[i_bb];
    const float* w_out   = (const float*)d_in[i_wout];
    const float* b_out   = (const float*)d_in[i_bout];
    const float* start_t = (const float*)d_in[i_st];
    const float* end_t   = (const float*)d_in[i_en];
    const float* trans   = (const float*)d_in[i_tr];
    float* out = (float*)d_out;

    cudaFuncSetAttribute(k2_persist, cudaFuncAttributeMaxDynamicSharedMemorySize, K2_SMEM);

    k1_proj<<<dim3(64, 256), 256>>>(tokens, emb, wih_f, b_f, wih_b, b_b);
    k2_persist<<<NCTA, 128, K2_SMEM>>>(whh_f, whh_b, lens);
    k3_feats<<<2048, 256>>>(w_out, b_out);
    k4_viterbi<<<64, 32>>>(start_t, end_t, trans, lens, out);
}